// round 17
// baseline (speedup 1.0000x reference)
#include <cuda_runtime.h>
#include <cuda_bf16.h>
#include <cstdint>

// ---------------------------------------------------------------------------
// TransformerBlock: windowed attention, B=4 C=192 H=W=256, 16x16 windows.
//   K0a: split W_qkv (576 rows) -> bf16 hi/lo; W_proj -> tf32 bits
//   K0b: x prepass — split each window's x into packed bf16 hi/lo planes
//   K1 : unified qkv (3x bf16), grid (6, 1024) M=96 tiles, 256 thr,
//        cp.async double-buffered pure-copy fills.
//   K2 : attention + fused proj (verbatim R16, cp.async pipelined)
// ---------------------------------------------------------------------------

constexpr int C_     = 192;
constexpr int NTOK   = 256;
constexpr int NWIN   = 1024;
constexpr int IMG    = 256 * 256;

__device__ uint32_t g_xh[(size_t)NWIN * C_ * 128];
__device__ uint32_t g_xl[(size_t)NWIN * C_ * 128];
__device__ uint32_t g_qh[(size_t)NWIN * C_ * 128];
__device__ uint32_t g_ql[(size_t)NWIN * C_ * 128];
__device__ uint32_t g_kh[(size_t)NWIN * C_ * 128];
__device__ uint32_t g_kl[(size_t)NWIN * C_ * 128];
__device__ uint32_t g_v [(size_t)NWIN * C_ * NTOK];
__device__ uint32_t g_wqkh[576 * 96];
__device__ uint32_t g_wqkl[576 * 96];
__device__ uint32_t g_wp[192 * 192];

__device__ __forceinline__ uint32_t f2tf(float x) {
    uint32_t u;
    asm("cvt.rna.tf32.f32 %0, %1;" : "=r"(u) : "f"(x));
    return u;
}
__device__ __forceinline__ void splitbf2(float x0, float x1, uint32_t& hi, uint32_t& lo) {
    __nv_bfloat16 h0 = __float2bfloat16_rn(x0);
    __nv_bfloat16 h1 = __float2bfloat16_rn(x1);
    __nv_bfloat16 l0 = __float2bfloat16_rn(x0 - __bfloat162float(h0));
    __nv_bfloat16 l1 = __float2bfloat16_rn(x1 - __bfloat162float(h1));
    hi = ((uint32_t)__bfloat16_as_ushort(h1) << 16) | __bfloat16_as_ushort(h0);
    lo = ((uint32_t)__bfloat16_as_ushort(l1) << 16) | __bfloat16_as_ushort(l0);
}
__device__ __forceinline__ uint32_t sptr(const void* p) {
    return (uint32_t)__cvta_generic_to_shared(p);
}
__device__ __forceinline__ void cpa16(uint32_t dst, const void* src) {
    asm volatile("cp.async.cg.shared.global [%0], [%1], 16;" :: "r"(dst), "l"(src));
}
#define CPA_COMMIT() asm volatile("cp.async.commit_group;" ::: "memory")
#define CPA_WAIT0()  asm volatile("cp.async.wait_group 0;" ::: "memory")
#define CPA_WAIT1()  asm volatile("cp.async.wait_group 1;" ::: "memory")

__device__ __forceinline__ void ldsm4(uint32_t* r, uint32_t a) {
    asm volatile("ldmatrix.sync.aligned.m8n8.x4.shared.b16 {%0,%1,%2,%3}, [%4];"
        : "=r"(r[0]), "=r"(r[1]), "=r"(r[2]), "=r"(r[3]) : "r"(a));
}
__device__ __forceinline__ void ldsm2(uint32_t* r, uint32_t a) {
    asm volatile("ldmatrix.sync.aligned.m8n8.x2.shared.b16 {%0,%1}, [%2];"
        : "=r"(r[0]), "=r"(r[1]) : "r"(a));
}
__device__ __forceinline__ void ldsm4t(uint32_t* r, uint32_t a) {
    asm volatile("ldmatrix.sync.aligned.m8n8.x4.trans.shared.b16 {%0,%1,%2,%3}, [%4];"
        : "=r"(r[0]), "=r"(r[1]), "=r"(r[2]), "=r"(r[3]) : "r"(a));
}
__device__ __forceinline__ void mma8(float* d, const uint32_t* a, const uint32_t* b) {
    asm volatile(
        "mma.sync.aligned.m16n8k8.row.col.f32.tf32.tf32.f32 "
        "{%0,%1,%2,%3}, {%4,%5,%6,%7}, {%8,%9}, {%0,%1,%2,%3};\n"
        : "+f"(d[0]), "+f"(d[1]), "+f"(d[2]), "+f"(d[3])
        : "r"(a[0]), "r"(a[1]), "r"(a[2]), "r"(a[3]),
          "r"(b[0]), "r"(b[1]));
}
__device__ __forceinline__ void mma16(float* d, const uint32_t* a, const uint32_t* b) {
    asm volatile(
        "mma.sync.aligned.m16n8k16.row.col.f32.bf16.bf16.f32 "
        "{%0,%1,%2,%3}, {%4,%5,%6,%7}, {%8,%9}, {%0,%1,%2,%3};\n"
        : "+f"(d[0]), "+f"(d[1]), "+f"(d[2]), "+f"(d[3])
        : "r"(a[0]), "r"(a[1]), "r"(a[2]), "r"(a[3]),
          "r"(b[0]), "r"(b[1]));
}

// ===========================================================================
// K0a: weights prepass.
// ===========================================================================
__global__ void split_w_kernel(const float* __restrict__ qkv_w,
                               const float* __restrict__ proj_w) {
    int idx = blockIdx.x * 256 + threadIdx.x;
    if (idx < 576 * 96) {
        int r = idx / 96, c = idx % 96;
        uint32_t h, l;
        splitbf2(qkv_w[r * C_ + 2 * c], qkv_w[r * C_ + 2 * c + 1], h, l);
        g_wqkh[idx] = h;
        g_wqkl[idx] = l;
    } else if (idx < 576 * 96 + 192 * 192) {
        int j = idx - 576 * 96;
        g_wp[j] = f2tf(proj_w[j]);
    }
}

// ===========================================================================
// K0b: x prepass.
// ===========================================================================
__global__ void __launch_bounds__(256) x_prepass(const float* __restrict__ x) {
    const int w = blockIdx.x;
    const int b = w >> 8, wh = (w >> 4) & 15, ww = w & 15;
    const float* xw = x + (size_t)b * C_ * IMG + (size_t)(wh * 16) * 256 + ww * 16;
    const size_t base = (size_t)w * C_ * 128;
    const int tid = threadIdx.x;
    for (int t = tid; t < 192 * 64; t += 256) {
        int ch = t >> 6, q = t & 63;
        int i = q >> 2, j4 = (q & 3) << 2;
        float4 v = *reinterpret_cast<const float4*>(xw + (size_t)ch * IMG + i * 256 + j4);
        int wi = (i * 16 + j4) >> 1;
        uint32_t h0, l0, h1, l1;
        splitbf2(v.x, v.y, h0, l0);
        splitbf2(v.z, v.w, h1, l1);
        g_xh[base + (size_t)ch * 128 + wi]     = h0;
        g_xh[base + (size_t)ch * 128 + wi + 1] = h1;
        g_xl[base + (size_t)ch * 128 + wi]     = l0;
        g_xl[base + (size_t)ch * 128 + wi + 1] = l1;
    }
}

// ===========================================================================
// K1: unified qkv (3x bf16). grid (6, 1024) M=96, 256 thr, 2 CTA/SM.
// smem words: Ah0[0,1920) Al0[1920,3840) Ah1[3840,5760) Al1[5760,7680)
//             Bh0[7680,11904) Bl0[11904,16128) Bh1[16128,20352) Bl1[20352,24576)
// ===========================================================================
constexpr int AS3 = 20;
constexpr int BT16 = 264;
constexpr size_t SMEM_QKV_BYTES = 24576u * 4;  // 98304

__global__ void __launch_bounds__(256, 2) qkv_kernel(const float* __restrict__ qkv_b) {
    extern __shared__ uint32_t smq[];

    const int w  = blockIdx.y;
    const int m0 = blockIdx.x * 96;
    const int tid = threadIdx.x, warp = tid >> 5, lane = tid & 31;
    const int wm = (warp >> 2) * 48;      // 0,48
    const int wn = (warp & 3) << 6;       // 0,64,128,192
    const uint32_t smb = sptr(smq);
    const uint32_t* xh = g_xh + (size_t)w * C_ * 128;
    const uint32_t* xl = g_xl + (size_t)w * C_ * 128;

    float acc[3][8][4];
#pragma unroll
    for (int i = 0; i < 3; i++)
#pragma unroll
        for (int j = 0; j < 8; j++)
#pragma unroll
            for (int r = 0; r < 4; r++) acc[i][j][r] = 0.f;

    auto issue_tile = [&](int t) {
        int bf = t & 1;
        uint32_t ah = smb + (bf * 3840) * 4;
        uint32_t al = smb + (1920 + bf * 3840) * 4;
        uint32_t bh = smb + (7680 + bf * 8448) * 4;
        uint32_t bl = smb + (11904 + bf * 8448) * 4;
        // A: 96 rows x 16 words per plane (384 cpa16 per plane)
#pragma unroll
        for (int i = tid; i < 384; i += 256) {
            int r = i >> 2, c4 = (i & 3) << 2;
            cpa16(ah + (r * AS3 + c4) * 4, &g_wqkh[(m0 + r) * 96 + t * 16 + c4]);
            cpa16(al + (r * AS3 + c4) * 4, &g_wqkl[(m0 + r) * 96 + t * 16 + c4]);
        }
        // B: 32 ch x 128 words per plane
#pragma unroll
        for (int i = tid; i < 1024; i += 256) {
            int r = i >> 5, c4 = (i & 31) << 2;
            cpa16(bh + (r * 132 + c4) * 4, xh + (size_t)(t * 32 + r) * 128 + c4);
            cpa16(bl + (r * 132 + c4) * 4, xl + (size_t)(t * 32 + r) * 128 + c4);
        }
        CPA_COMMIT();
    };

    issue_tile(0);
    issue_tile(1);

    const int arow0 = (lane & 7) + ((lane & 8) ? 8 : 0);
    const int asel = (lane & 16) ? 4 : 0;
    const int brow0 = (lane & 7) + ((lane & 8) ? 8 : 0);
    const int bsel = (lane & 16) ? 8 : 0;

    for (int cb = 0; cb < 6; cb++) {
        if (cb < 5) { CPA_WAIT1(); } else { CPA_WAIT0(); }
        __syncthreads();

        int bf = cb & 1;
        uint32_t* Ah = smq + bf * 3840;
        uint32_t* Al = Ah + 1920;
        uint16_t* Bh16 = (uint16_t*)(smq + 7680 + bf * 8448);
        uint16_t* Bl16 = (uint16_t*)(smq + 11904 + bf * 8448);

#pragma unroll
        for (int kk = 0; kk < 32; kk += 16) {
            uint32_t ah[3][4], al[3][4];
            int awrd = (kk >> 1) + asel;
#pragma unroll
            for (int i = 0; i < 3; i++) {
                int r = wm + i * 16 + arow0;
                ldsm4(ah[i], sptr(&Ah[r * AS3 + awrd]));
                ldsm4(al[i], sptr(&Al[r * AS3 + awrd]));
            }
            int brow = kk + brow0;
#pragma unroll
            for (int inp = 0; inp < 4; inp++) {
                int n0 = wn + inp * 16 + bsel;
                uint32_t bh4[4], bl4[4];
                ldsm4t(bh4, sptr(&Bh16[brow * BT16 + n0]));
                ldsm4t(bl4, sptr(&Bl16[brow * BT16 + n0]));
#pragma unroll
                for (int i = 0; i < 3; i++) {
                    mma16(acc[i][2 * inp],     ah[i], bl4);
                    mma16(acc[i][2 * inp],     al[i], bh4);
                    mma16(acc[i][2 * inp],     ah[i], bh4);
                    mma16(acc[i][2 * inp + 1], ah[i], bl4 + 2);
                    mma16(acc[i][2 * inp + 1], al[i], bh4 + 2);
                    mma16(acc[i][2 * inp + 1], ah[i], bh4 + 2);
                }
            }
        }
        __syncthreads();
        if (cb < 4) issue_tile(cb + 2);
    }

    if (m0 < 384) {
        // q/k epilogue: +bias, split to packed bf16 hi/lo planes [ch][tok/2]
        const int sec = m0 / 192;
        const int ob  = m0 % 192;
        uint32_t* dh = (sec == 0) ? g_qh : g_kh;
        uint32_t* dl = (sec == 0) ? g_ql : g_kl;
        const size_t base = (size_t)w * C_ * 128;
#pragma unroll
        for (int im = 0; im < 3; im++) {
            int mr = wm + im * 16 + (lane >> 2);
            float b0 = qkv_b[m0 + mr];
            float b1 = qkv_b[m0 + mr + 8];
#pragma unroll
            for (int in = 0; in < 8; in++) {
                int n0 = wn + in * 8 + ((lane & 3) << 1);
                int wi = n0 >> 1;
                uint32_t h, l;
                splitbf2(acc[im][in][0] + b0, acc[im][in][1] + b0, h, l);
                dh[base + (size_t)(ob + mr) * 128 + wi] = h;
                dl[base + (size_t)(ob + mr) * 128 + wi] = l;
                splitbf2(acc[im][in][2] + b1, acc[im][in][3] + b1, h, l);
                dh[base + (size_t)(ob + mr + 8) * 128 + wi] = h;
                dl[base + (size_t)(ob + mr + 8) * 128 + wi] = l;
            }
        }
    } else {
        // v epilogue: +bias, tf32 bits [ch][tok]
        const int ob = m0 - 384;
        const size_t base = (size_t)w * C_ * NTOK;
#pragma unroll
        for (int im = 0; im < 3; im++) {
            int mr = wm + im * 16 + (lane >> 2);
            float b0 = qkv_b[m0 + mr];
            float b1 = qkv_b[m0 + mr + 8];
#pragma unroll
            for (int in = 0; in < 8; in++) {
                int n0 = wn + in * 8 + ((lane & 3) << 1);
                uint2 r0, r1;
                r0.x = f2tf(acc[im][in][0] + b0); r0.y = f2tf(acc[im][in][1] + b0);
                r1.x = f2tf(acc[im][in][2] + b1); r1.y = f2tf(acc[im][in][3] + b1);
                *reinterpret_cast<uint2*>(&g_v[base + (size_t)(ob + mr) * NTOK + n0])     = r0;
                *reinterpret_cast<uint2*>(&g_v[base + (size_t)(ob + mr + 8) * NTOK + n0]) = r1;
            }
        }
    }
}

// ===========================================================================
// K2: attention + fused proj. grid (4, 1024), 512 thr. smem 232448 B. (R16)
// ===========================================================================
constexpr int QST = 72;
constexpr int KST = 72;
constexpr int VST = 68;
constexpr int SSS = 260;
constexpr int OS2 = 196;
constexpr size_t SMEM_ATTN_BYTES = 58112u * 4;   // 232448

__global__ void __launch_bounds__(512, 1) attn_kernel(const float* __restrict__ x,
                                                      const float* __restrict__ proj_b,
                                                      float* __restrict__ out) {
    extern __shared__ uint32_t sm[];
    uint16_t* Qh16 = (uint16_t*)sm;
    uint16_t* Ql16 = (uint16_t*)(sm + 6912);
    uint32_t* Ssm  = sm + 41472;
    uint32_t* Osm  = sm;
    uint32_t* Wsm  = sm + 13824;

    const int qb = blockIdx.x, w = blockIdx.y;
    const int b  = w >> 8, wh = (w >> 4) & 15, ww = w & 15;
    const int tid = threadIdx.x, warp = tid >> 5, lane = tid & 31;

    const uint32_t smb = sptr(sm);
    const uint32_t* gqh = g_qh + (size_t)w * C_ * 128 + qb * 32;
    const uint32_t* gql = g_ql + (size_t)w * C_ * 128 + qb * 32;
    const uint32_t* gkh = g_kh + (size_t)w * C_ * 128;
    const uint32_t* gkl = g_kl + (size_t)w * C_ * 128;

    {
        for (int t = tid; t < 1536; t += 512) {
            int r = t >> 3, c4 = (t & 7) << 2;
            cpa16(smb + (r * 36 + c4) * 4,          gqh + (size_t)r * 128 + c4);
            cpa16(smb + (6912 + r * 36 + c4) * 4,   gql + (size_t)r * 128 + c4);
        }
        for (int t = tid; t < 1536; t += 512) {
            int r = t >> 3, c4 = (t & 7) << 2;
            cpa16(smb + (13824 + r * 36 + c4) * 4, gkh + (size_t)r * 128 + c4);
            cpa16(smb + (20736 + r * 36 + c4) * 4, gkl + (size_t)r * 128 + c4);
        }
        CPA_COMMIT();
        for (int t = tid; t < 1536; t += 512) {
            int r = t >> 3, c4 = (t & 7) << 2;
            cpa16(smb + (27648 + r * 36 + c4) * 4, gkh + (size_t)r * 128 + 32 + c4);
            cpa16(smb + (34560 + r * 36 + c4) * 4, gkl + (size_t)r * 128 + 32 + c4);
        }
        CPA_COMMIT();
    }

    const int wmS = (warp >> 2) << 4;
    const int wkS = (warp & 3) << 4;
    const int qk_r = (lane & 7) + ((lane & 16) ? 8 : 0);
    const int qtok = (lane & 8) ? 8 : 0;
    const int kk_r = (lane & 7) + ((lane & 8) ? 8 : 0);
    const int ksel = (lane & 16) ? 8 : 0;

    for (int cb = 0; cb < 4; cb++) {
        if (cb < 3) { CPA_WAIT1(); } else { CPA_WAIT0(); }
        __syncthreads();

        const uint16_t* KhB = (const uint16_t*)(sm + 13824 + (cb & 1) * 13824);
        const uint16_t* KlB = (const uint16_t*)(sm + 20736 + (cb & 1) * 13824);

        float sacc[2][4];
#pragma unroll
        for (int j = 0; j < 2; j++)
#pragma unroll
            for (int r = 0; r < 4; r++) sacc[j][r] = 0.f;

#pragma unroll
        for (int kk2 = 0; kk2 < 192; kk2 += 16) {
            uint32_t ah[4], al[4], bh4[4], bl4[4];
            int col = wmS + qtok;
            ldsm4t(ah, sptr(&Qh16[(kk2 + qk_r) * QST + col]));
            ldsm4t(al, sptr(&Ql16[(kk2 + qk_r) * QST + col]));
            ldsm4t(bh4, sptr(&KhB[(kk2 + kk_r) * KST + wkS + ksel]));
            ldsm4t(bl4, sptr(&KlB[(kk2 + kk_r) * KST + wkS + ksel]));
            mma16(sacc[0], ah, bl4);
            mma16(sacc[0], al, bh4);
            mma16(sacc[0], ah, bh4);
            mma16(sacc[1], ah, bl4 + 2);
            mma16(sacc[1], al, bh4 + 2);
            mma16(sacc[1], ah, bh4 + 2);
        }
        {
            int r0 = wmS + (lane >> 2);
#pragma unroll
            for (int in = 0; in < 2; in++) {
                int c0 = cb * 64 + wkS + in * 8 + ((lane & 3) << 1);
                Ssm[r0 * SSS + c0]           = __float_as_uint(sacc[in][0]);
                Ssm[r0 * SSS + c0 + 1]       = __float_as_uint(sacc[in][1]);
                Ssm[(r0 + 8) * SSS + c0]     = __float_as_uint(sacc[in][2]);
                Ssm[(r0 + 8) * SSS + c0 + 1] = __float_as_uint(sacc[in][3]);
            }
        }
        __syncthreads();

        if (cb < 2) {
            int c = cb + 2;
            uint32_t bh = smb + (13824 + (cb & 1) * 13824) * 4;
            uint32_t bl = smb + (20736 + (cb & 1) * 13824) * 4;
            for (int t = tid; t < 1536; t += 512) {
                int r = t >> 3, c4 = (t & 7) << 2;
                cpa16(bh + (r * 36 + c4) * 4, gkh + (size_t)r * 128 + c * 32 + c4);
                cpa16(bl + (r * 36 + c4) * 4, gkl + (size_t)r * 128 + c * 32 + c4);
            }
            CPA_COMMIT();
        }
    }

    const uint32_t* gv = g_v + (size_t)w * C_ * NTOK;
    for (int t = tid; t < 3072; t += 512) {
        int r = t >> 4, c4 = (t & 15) << 2;
        cpa16(smb + (13824 + r * VST + c4) * 4, gv + (size_t)r * 256 + c4);
    }
    CPA_COMMIT();
    for (int t = tid; t < 3072; t += 512) {
        int r = t >> 4, c4 = (t & 15) << 2;
        cpa16(smb + (26880 + r * VST + c4) * 4, gv + (size_t)r * 256 + 64 + c4);
    }
    CPA_COMMIT();

#pragma unroll
    for (int rr = 0; rr < 4; rr++) {
        int row = warp * 4 + rr;
        float v[8];
        float mx = -3.0e38f;
#pragma unroll
        for (int i = 0; i < 8; i++) {
            v[i] = __uint_as_float(Ssm[row * SSS + lane + (i << 5)]);
            mx = fmaxf(mx, v[i]);
        }
#pragma unroll
        for (int off = 16; off; off >>= 1) mx = fmaxf(mx, __shfl_xor_sync(0xffffffffu, mx, off));
        float sum = 0.f;
#pragma unroll
        for (int i = 0; i < 8; i++) { v[i] = __expf(v[i] - mx); sum += v[i]; }
#pragma unroll
        for (int off = 16; off; off >>= 1) sum += __shfl_xor_sync(0xffffffffu, sum, off);
        float inv = 1.0f / sum;
#pragma unroll
        for (int i = 0; i < 8; i++) Ssm[row * SSS + lane + (i << 5)] = f2tf(v[i] * inv);
    }

    const int wm2 = (warp >> 3) << 5;
    const int wc = (warp & 7) * 24;
    const int arow = wm2 + (lane & 7) + ((lane & 8) ? 8 : 0);
    const int asel = (lane & 16) ? 4 : 0;
    const int vrow = (lane & 7) + ((lane & 16) ? 8 : 0);
    const int vkw  = (lane & 8) ? 4 : 0;
    float oacc[2][3][4];
#pragma unroll
    for (int i = 0; i < 2; i++)
#pragma unroll
        for (int j = 0; j < 3; j++)
#pragma unroll
            for (int r = 0; r < 4; r++) oacc[i][j][r] = 0.f;

    for (int vb = 0; vb < 4; vb++) {
        if (vb < 3) { CPA_WAIT1(); } else { CPA_WAIT0(); }
        __syncthreads();

        const uint32_t* Vs = sm + 13824 + (vb & 1) * 13056;

#pragma unroll
        for (int kk = 0; kk < 64; kk += 8) {
            uint32_t a[2][4], b4[4], b2[2];
            int awrd = vb * 64 + kk + asel;
            ldsm4(a[0], sptr(&Ssm[arow * SSS + awrd]));
            ldsm4(a[1], sptr(&Ssm[(arow + 16) * SSS + awrd]));
            ldsm4(b4, sptr(&Vs[(wc + vrow) * VST + kk + vkw]));
            ldsm2(b2, sptr(&Vs[(wc + 16 + (lane & 7)) * VST + kk + vkw]));
#pragma unroll
            for (int im = 0; im < 2; im++) {
                mma8(oacc[im][0], a[im], b4);
                mma8(oacc[im][1], a[im], b4 + 2);
                mma8(oacc[im][2], a[im], b2);
            }
        }
        __syncthreads();

        if (vb < 2) {
            int c = vb + 2;
            uint32_t bb = smb + (13824 + (vb & 1) * 13056) * 4;
            for (int t = tid; t < 3072; t += 512) {
                int r = t >> 4, c4 = (t & 15) << 2;
                cpa16(bb + (r * VST + c4) * 4, gv + (size_t)r * 256 + c * 64 + c4);
            }
            CPA_COMMIT();
        }
    }

#pragma unroll
    for (int im = 0; im < 2; im++) {
        int q0 = wm2 + im * 16 + (lane >> 2);
#pragma unroll
        for (int in = 0; in < 3; in++) {
            int c0 = wc + in * 8 + ((lane & 3) << 1);
            Osm[q0 * OS2 + c0]           = f2tf(oacc[im][in][0]);
            Osm[q0 * OS2 + c0 + 1]       = f2tf(oacc[im][in][1]);
            Osm[(q0 + 8) * OS2 + c0]     = f2tf(oacc[im][in][2]);
            Osm[(q0 + 8) * OS2 + c0 + 1] = f2tf(oacc[im][in][3]);
        }
    }
#pragma unroll
    for (int t = tid; t < 192 * 12; t += 512) {
        int r = t / 12, c4 = (t % 12) << 2;
        *reinterpret_cast<uint4*>(&Wsm[r * OS2 + c4]) =
            *reinterpret_cast<const uint4*>(&g_wp[r * C_ + c4]);
        *reinterpret_cast<uint4*>(&Wsm[r * OS2 + c4 + 48]) =
            *reinterpret_cast<const uint4*>(&g_wp[r * C_ + c4 + 48]);
        *reinterpret_cast<uint4*>(&Wsm[r * OS2 + c4 + 96]) =
            *reinterpret_cast<const uint4*>(&g_wp[r * C_ + c4 + 96]);
        *reinterpret_cast<uint4*>(&Wsm[r * OS2 + c4 + 144]) =
            *reinterpret_cast<const uint4*>(&g_wp[r * C_ + c4 + 144]);
    }
    __syncthreads();

    const int wmp = (warp & 3) * 48;
    const int wnp = (warp >> 2) * 16;
    const int parow = (lane & 7) + ((lane & 8) ? 8 : 0);
    const int pasel = (lane & 16) ? 4 : 0;
    const int pbrow = (lane & 7) + ((lane & 16) ? 8 : 0);
    const int pbkw = (lane & 8) ? 4 : 0;

    float pacc[3][2][4];
#pragma unroll
    for (int i = 0; i < 3; i++)
#pragma unroll
        for (int j = 0; j < 2; j++)
#pragma unroll
            for (int r = 0; r < 4; r++) pacc[i][j][r] = 0.f;

#pragma unroll
    for (int kk = 0; kk < 192; kk += 8) {
        uint32_t a[3][4], b4[4];
#pragma unroll
        for (int i = 0; i < 3; i++)
            ldsm4(a[i], sptr(&Wsm[(wmp + i * 16 + parow) * OS2 + kk + pasel]));
        ldsm4(b4, sptr(&Osm[(wnp + pbrow) * OS2 + kk + pbkw]));
#pragma unroll
        for (int i = 0; i < 3; i++) {
            mma8(pacc[i][0], a[i], b4);
            mma8(pacc[i][1], a[i], b4 + 2);
        }
    }

#pragma unroll
    for (int i = 0; i < 3; i++) {
        int ch = wmp + i * 16 + (lane >> 2);
        float b0 = proj_b[ch];
        float b1 = proj_b[ch + 8];
#pragma unroll
        for (int j = 0; j < 2; j++) {
            int tok = qb * 64 + wnp + j * 8 + ((lane & 3) << 1);
            int ti = tok >> 4, tj = tok & 15;
            size_t g0 = (((size_t)b * C_ + ch) * 256 + wh * 16 + ti) * 256 + ww * 16 + tj;
            size_t g1 = (((size_t)b * C_ + ch + 8) * 256 + wh * 16 + ti) * 256 + ww * 16 + tj;
            float2 x0 = *reinterpret_cast<const float2*>(&x[g0]);
            float2 x1 = *reinterpret_cast<const float2*>(&x[g1]);
            float2 r0, r1;
            r0.x = pacc[i][j][0] + b0 + x0.x;
            r0.y = pacc[i][j][1] + b0 + x0.y;
            r1.x = pacc[i][j][2] + b1 + x1.x;
            r1.y = pacc[i][j][3] + b1 + x1.y;
            *reinterpret_cast<float2*>(&out[g0]) = r0;
            *reinterpret_cast<float2*>(&out[g1]) = r1;
        }
    }
}

// ---------------------------------------------------------------------------
namespace {
struct WarmUp {
    WarmUp() {
        void* p = nullptr;
        cudaGetSymbolAddress(&p, g_xh);
        cudaGetSymbolAddress(&p, g_xl);
        cudaGetSymbolAddress(&p, g_qh);
        cudaGetSymbolAddress(&p, g_ql);
        cudaGetSymbolAddress(&p, g_kh);
        cudaGetSymbolAddress(&p, g_kl);
        cudaGetSymbolAddress(&p, g_v);
        cudaGetSymbolAddress(&p, g_wqkh);
        cudaGetSymbolAddress(&p, g_wqkl);
        cudaGetSymbolAddress(&p, g_wp);
        cudaFuncSetAttribute(attn_kernel, cudaFuncAttributeMaxDynamicSharedMemorySize,
                             (int)SMEM_ATTN_BYTES);
        cudaFuncSetAttribute(qkv_kernel, cudaFuncAttributeMaxDynamicSharedMemorySize,
                             (int)SMEM_QKV_BYTES);
    }
};
WarmUp warm_;
}  // namespace

extern "C" void kernel_launch(void* const* d_in, const int* in_sizes, int n_in,
                              void* d_out, int out_size) {
    (void)in_sizes; (void)n_in; (void)out_size;
    const float* x      = (const float*)d_in[0];
    const float* qkv_w  = (const float*)d_in[1];
    const float* qkv_b  = (const float*)d_in[2];
    const float* proj_w = (const float*)d_in[3];
    const float* proj_b = (const float*)d_in[4];
    float* out = (float*)d_out;

    cudaFuncSetAttribute(attn_kernel, cudaFuncAttributeMaxDynamicSharedMemorySize,
                         (int)SMEM_ATTN_BYTES);
    cudaFuncSetAttribute(qkv_kernel, cudaFuncAttributeMaxDynamicSharedMemorySize,
                         (int)SMEM_QKV_BYTES);

    split_w_kernel<<<360, 256>>>(qkv_w, proj_w);
    x_prepass<<<NWIN, 256>>>(x);
    qkv_kernel<<<dim3(6, NWIN), 256, SMEM_QKV_BYTES>>>(qkv_b);
    attn_kernel<<<dim3(4, NWIN), 512, SMEM_ATTN_BYTES>>>(x, proj_b, out);
}